// round 2
// baseline (speedup 1.0000x reference)
#include <cuda_runtime.h>
#include <cuda_bf16.h>
#include <math.h>

#define N_BINS 15

// Global scratch accumulators
__device__ double g_count[N_BINS];
__device__ double g_conf[N_BINS];
__device__ double g_acc[N_BINS];
__device__ double g_bri;

__global__ void ece_init() {
    int t = threadIdx.x;
    if (t < N_BINS) { g_count[t] = 0.0; g_conf[t] = 0.0; g_acc[t] = 0.0; }
    if (t == 0) g_bri = 0.0;
}

// Specialized for C == 100: warp-per-row, 25 x float4 per row.
__global__ void ece_main_c100(const float4* __restrict__ probs4,
                              const int* __restrict__ labels,
                              int N) {
    const int lane  = threadIdx.x & 31;
    const int warp  = (blockIdx.x * blockDim.x + threadIdx.x) >> 5;
    const int nwarp = (gridDim.x * blockDim.x) >> 5;

    float acc_count = 0.f, acc_conf = 0.f, acc_acc = 0.f;  // lane b owns bin b (b<15)
    float acc_bri = 0.f;                                   // lane 0 owns brier sum

    for (int row = warp; row < N; row += nwarp) {
        const float4* rp = probs4 + (size_t)row * 25;
        float4 v;
        if (lane < 25) v = rp[lane];
        else           v = make_float4(0.f, 0.f, 0.f, 0.f);

        // lane-local stats
        float s  = (v.x + v.y) + (v.z + v.w);
        float sq = (v.x * v.x + v.y * v.y) + (v.z * v.z + v.w * v.w);
        float m  = -1.f;
        int   mi = 0x7fffffff;
        if (lane < 25) {
            int base = lane * 4;
            m = v.x; mi = base;
            if (v.y > m) { m = v.y; mi = base + 1; }
            if (v.z > m) { m = v.z; mi = base + 2; }
            if (v.w > m) { m = v.w; mi = base + 3; }
        }

        // butterfly reductions (all lanes converge to the same result)
        #pragma unroll
        for (int off = 16; off >= 1; off >>= 1) {
            s  += __shfl_xor_sync(0xffffffffu, s,  off);
            sq += __shfl_xor_sync(0xffffffffu, sq, off);
            float om = __shfl_xor_sync(0xffffffffu, m,  off);
            int   oi = __shfl_xor_sync(0xffffffffu, mi, off);
            if (om > m || (om == m && oi < mi)) { m = om; mi = oi; }
        }

        int lab = labels[row];                         // int32 labels
        int labc = lab < 0 ? 0 : (lab > 99 ? 99 : lab);   // crash-proof gather
        float pl = __ldg((const float*)probs4 + (size_t)row * 100 + labc);

        float inv  = 1.f / s;
        float conf = m * inv;
        float bri  = sq * inv * inv - 2.f * pl * inv + 1.f;
        int   hit  = (mi == lab) ? 1 : 0;

        int bin = (int)ceilf(conf * (float)N_BINS) - 1;
        bin = bin < 0 ? 0 : (bin > N_BINS - 1 ? N_BINS - 1 : bin);

        if (lane == bin) {
            acc_count += 1.f;
            acc_conf  += conf;
            acc_acc   += (float)hit;
        }
        if (lane == 0) acc_bri += bri;
    }

    if (lane < N_BINS && acc_count > 0.f) {
        atomicAdd(&g_count[lane], (double)acc_count);
        atomicAdd(&g_conf[lane],  (double)acc_conf);
        atomicAdd(&g_acc[lane],   (double)acc_acc);
    }
    if (lane == 0 && acc_bri != 0.f) atomicAdd(&g_bri, (double)acc_bri);
}

// Generic fallback (any C): warp-per-row, strided scalar loads.
__global__ void ece_main_generic(const float* __restrict__ probs,
                                 const int* __restrict__ labels,
                                 int N, int C) {
    const int lane  = threadIdx.x & 31;
    const int warp  = (blockIdx.x * blockDim.x + threadIdx.x) >> 5;
    const int nwarp = (gridDim.x * blockDim.x) >> 5;

    float acc_count = 0.f, acc_conf = 0.f, acc_acc = 0.f, acc_bri = 0.f;

    for (int row = warp; row < N; row += nwarp) {
        const float* rp = probs + (size_t)row * C;
        float s = 0.f, sq = 0.f, m = -1.f;
        int mi = 0x7fffffff;
        for (int c = lane; c < C; c += 32) {
            float x = rp[c];
            s += x; sq += x * x;
            if (x > m) { m = x; mi = c; }
        }
        #pragma unroll
        for (int off = 16; off >= 1; off >>= 1) {
            s  += __shfl_xor_sync(0xffffffffu, s,  off);
            sq += __shfl_xor_sync(0xffffffffu, sq, off);
            float om = __shfl_xor_sync(0xffffffffu, m,  off);
            int   oi = __shfl_xor_sync(0xffffffffu, mi, off);
            if (om > m || (om == m && oi < mi)) { m = om; mi = oi; }
        }
        int lab = labels[row];
        int labc = lab < 0 ? 0 : (lab >= C ? C - 1 : lab);
        float pl = rp[labc];
        float inv  = 1.f / s;
        float conf = m * inv;
        float bri  = sq * inv * inv - 2.f * pl * inv + 1.f;
        int   hit  = (mi == lab) ? 1 : 0;
        int bin = (int)ceilf(conf * (float)N_BINS) - 1;
        bin = bin < 0 ? 0 : (bin > N_BINS - 1 ? N_BINS - 1 : bin);
        if (lane == bin) { acc_count += 1.f; acc_conf += conf; acc_acc += (float)hit; }
        if (lane == 0) acc_bri += bri;
    }

    if (lane < N_BINS && acc_count > 0.f) {
        atomicAdd(&g_count[lane], (double)acc_count);
        atomicAdd(&g_conf[lane],  (double)acc_conf);
        atomicAdd(&g_acc[lane],   (double)acc_acc);
    }
    if (lane == 0 && acc_bri != 0.f) atomicAdd(&g_bri, (double)acc_bri);
}

__global__ void ece_final(float* __restrict__ out, int N) {
    if (threadIdx.x == 0) {
        double ece = 0.0, mx = 0.0;
        double invN = 1.0 / (double)N;
        #pragma unroll
        for (int b = 0; b < N_BINS; b++) {
            double c = g_count[b];
            if (c > 0.0) {
                double gap = fabs(g_conf[b] / c - g_acc[b] / c);
                ece += gap * c * invN;
                if (gap > mx) mx = gap;
            }
        }
        out[0] = (float)ece;
        out[1] = (float)mx;
        out[2] = (float)(g_bri * invN);
    }
}

extern "C" void kernel_launch(void* const* d_in, const int* in_sizes, int n_in,
                              void* d_out, int out_size) {
    // Identify inputs by size: probs is the big one.
    int i_probs = 0, i_labels = 1;
    if (n_in >= 2 && in_sizes[1] > in_sizes[0]) { i_probs = 1; i_labels = 0; }
    const float* probs  = (const float*)d_in[i_probs];
    const int*   labels = (const int*)d_in[i_labels];
    int N = in_sizes[i_labels];
    int C = in_sizes[i_probs] / N;
    float* out = (float*)d_out;

    ece_init<<<1, 32>>>();

    const int threads = 256;
    const int blocks  = 148 * 8;  // ~9.5K warps, ~105 rows/warp
    if (C == 100) {
        ece_main_c100<<<blocks, threads>>>((const float4*)probs, labels, N);
    } else {
        ece_main_generic<<<blocks, threads>>>(probs, labels, N, C);
    }

    ece_final<<<1, 32>>>(out, N);
}

// round 3
// speedup vs baseline: 2.0172x; 2.0172x over previous
#include <cuda_runtime.h>
#include <cuda_bf16.h>
#include <math.h>

#define N_BINS 15

__device__ double g_count[N_BINS];
__device__ double g_conf[N_BINS];
__device__ double g_acc[N_BINS];
__device__ double g_bri;

__global__ void ece_init() {
    int t = threadIdx.x;
    if (t < N_BINS) { g_count[t] = 0.0; g_conf[t] = 0.0; g_acc[t] = 0.0; }
    if (t == 0) g_bri = 0.0;
}

// C==100 specialized: 8 lanes per row, 4 rows per warp, double-buffered.
__global__ void __launch_bounds__(256) ece_main_c100(
    const float4* __restrict__ probs4,
    const int* __restrict__ labels,
    int N)
{
    const int lane  = threadIdx.x & 31;
    const int k     = lane & 7;          // lane within row-group
    const int g     = lane >> 3;         // row-group (0..3)
    const int gbase = lane & 24;         // group's base lane
    const int warp  = (blockIdx.x * blockDim.x + threadIdx.x) >> 5;
    const int nwarp = (gridDim.x * blockDim.x) >> 5;
    const int step  = nwarp * 4;

    // per-lane bin accumulators: set A owns bin k, set B owns bin k+8 (k<7)
    float a_cnt = 0.f, a_cf = 0.f, a_ac = 0.f;
    float b_cnt = 0.f, b_cf = 0.f, b_ac = 0.f;
    float abri  = 0.f;

    float4 c0, c1, c2, c3;   // current quad, this lane's slots
    float4 n0, n1, n2, n3;   // next quad
    int clab = 0, nlab = 0;
    bool cval = false, nval = false;

    int q0 = warp * 4;

    // prologue load
    {
        int row = q0 + g;
        cval = (q0 < N) && (row < N);
        if (cval) {
            const float4* rp = probs4 + (size_t)row * 25;
            c0 = rp[k]; c1 = rp[k + 8]; c2 = rp[k + 16];
            c3 = (k == 0) ? rp[24] : make_float4(0.f, 0.f, 0.f, 0.f);
            clab = labels[row];
        } else {
            c0 = c1 = c2 = c3 = make_float4(0.f, 0.f, 0.f, 0.f);
        }
    }

    for (int q = q0; q < N; q += step) {
        // prefetch next quad
        int nq = q + step;
        int nrow = nq + g;
        nval = (nq < N) && (nrow < N);
        if (nval) {
            const float4* rp = probs4 + (size_t)nrow * 25;
            n0 = rp[k]; n1 = rp[k + 8]; n2 = rp[k + 16];
            n3 = (k == 0) ? rp[24] : make_float4(0.f, 0.f, 0.f, 0.f);
            nlab = labels[nrow];
        }

        // ---- process current quad ----
        float s, sq, m; int mi;
        {   // slot 0: elements 4k .. 4k+3
            int base = k * 4;
            s  = (c0.x + c0.y) + (c0.z + c0.w);
            sq = (c0.x * c0.x + c0.y * c0.y) + (c0.z * c0.z + c0.w * c0.w);
            m = c0.x; mi = base;
            if (c0.y > m) { m = c0.y; mi = base + 1; }
            if (c0.z > m) { m = c0.z; mi = base + 2; }
            if (c0.w > m) { m = c0.w; mi = base + 3; }
        }
        {   // slot 1: elements 4(k+8) ..
            int base = (k + 8) * 4;
            s  += (c1.x + c1.y) + (c1.z + c1.w);
            sq += (c1.x * c1.x + c1.y * c1.y) + (c1.z * c1.z + c1.w * c1.w);
            if (c1.x > m) { m = c1.x; mi = base; }
            if (c1.y > m) { m = c1.y; mi = base + 1; }
            if (c1.z > m) { m = c1.z; mi = base + 2; }
            if (c1.w > m) { m = c1.w; mi = base + 3; }
        }
        {   // slot 2: elements 4(k+16) ..
            int base = (k + 16) * 4;
            s  += (c2.x + c2.y) + (c2.z + c2.w);
            sq += (c2.x * c2.x + c2.y * c2.y) + (c2.z * c2.z + c2.w * c2.w);
            if (c2.x > m) { m = c2.x; mi = base; }
            if (c2.y > m) { m = c2.y; mi = base + 1; }
            if (c2.z > m) { m = c2.z; mi = base + 2; }
            if (c2.w > m) { m = c2.w; mi = base + 3; }
        }
        if (k == 0) {  // slot 3: elements 96..99 (only lane 0 of group)
            s  += (c3.x + c3.y) + (c3.z + c3.w);
            sq += (c3.x * c3.x + c3.y * c3.y) + (c3.z * c3.z + c3.w * c3.w);
            if (c3.x > m) { m = c3.x; mi = 96; }
            if (c3.y > m) { m = c3.y; mi = 97; }
            if (c3.z > m) { m = c3.z; mi = 98; }
            if (c3.w > m) { m = c3.w; mi = 99; }
        }

        // reduce within 8-lane group
        #pragma unroll
        for (int off = 4; off >= 1; off >>= 1) {
            s  += __shfl_xor_sync(0xffffffffu, s,  off);
            sq += __shfl_xor_sync(0xffffffffu, sq, off);
            float om = __shfl_xor_sync(0xffffffffu, m,  off);
            int   oi = __shfl_xor_sync(0xffffffffu, mi, off);
            if (om > m || (om == m && oi < mi)) { m = om; mi = oi; }
        }

        // p[label] from registers via shuffle (all group lanes share clab)
        int lab  = clab;
        int labc = lab < 0 ? 0 : (lab > 99 ? 99 : lab);
        int idx4 = labc >> 2, comp = labc & 3;
        int slot = idx4 >> 3;
        int owner = (slot == 3) ? 0 : (idx4 & 7);
        float4 vs = (slot == 0) ? c0 : (slot == 1) ? c1 : (slot == 2) ? c2 : c3;
        float cand = (comp == 0) ? vs.x : (comp == 1) ? vs.y : (comp == 2) ? vs.z : vs.w;
        float pl = __shfl_sync(0xffffffffu, cand, gbase | owner);

        float inv  = 1.f / s;
        float conf = m * inv;
        float bri  = sq * inv * inv - 2.f * pl * inv + 1.f;
        float hit  = (mi == lab) ? 1.f : 0.f;
        int bin = (int)ceilf(conf * (float)N_BINS) - 1;
        bin = bin < 0 ? 0 : (bin > N_BINS - 1 ? N_BINS - 1 : bin);

        if (cval) {
            if (bin == k)     { a_cnt += 1.f; a_cf += conf; a_ac += hit; }
            if (bin == k + 8) { b_cnt += 1.f; b_cf += conf; b_ac += hit; }
            if (k == 0) abri += bri;
        }

        // rotate buffers
        c0 = n0; c1 = n1; c2 = n2; c3 = n3; clab = nlab; cval = nval;
    }

    // cross-group reduction (groups differ by lane bits 3,4)
    #pragma unroll
    for (int off = 8; off <= 16; off <<= 1) {
        a_cnt += __shfl_xor_sync(0xffffffffu, a_cnt, off);
        a_cf  += __shfl_xor_sync(0xffffffffu, a_cf,  off);
        a_ac  += __shfl_xor_sync(0xffffffffu, a_ac,  off);
        b_cnt += __shfl_xor_sync(0xffffffffu, b_cnt, off);
        b_cf  += __shfl_xor_sync(0xffffffffu, b_cf,  off);
        b_ac  += __shfl_xor_sync(0xffffffffu, b_ac,  off);
        abri  += __shfl_xor_sync(0xffffffffu, abri,  off);
    }

    if (lane < 8 && a_cnt > 0.f) {
        atomicAdd(&g_count[lane], (double)a_cnt);
        atomicAdd(&g_conf[lane],  (double)a_cf);
        atomicAdd(&g_acc[lane],   (double)a_ac);
    }
    if (lane < 7 && b_cnt > 0.f) {
        atomicAdd(&g_count[lane + 8], (double)b_cnt);
        atomicAdd(&g_conf[lane + 8],  (double)b_cf);
        atomicAdd(&g_acc[lane + 8],   (double)b_ac);
    }
    if (lane == 0 && abri != 0.f) atomicAdd(&g_bri, (double)abri);
}

// Generic fallback (any C): warp-per-row.
__global__ void ece_main_generic(const float* __restrict__ probs,
                                 const int* __restrict__ labels,
                                 int N, int C) {
    const int lane  = threadIdx.x & 31;
    const int warp  = (blockIdx.x * blockDim.x + threadIdx.x) >> 5;
    const int nwarp = (gridDim.x * blockDim.x) >> 5;

    float acc_count = 0.f, acc_conf = 0.f, acc_acc = 0.f, acc_bri = 0.f;

    for (int row = warp; row < N; row += nwarp) {
        const float* rp = probs + (size_t)row * C;
        float s = 0.f, sq = 0.f, m = -1.f;
        int mi = 0x7fffffff;
        for (int c = lane; c < C; c += 32) {
            float x = rp[c];
            s += x; sq += x * x;
            if (x > m) { m = x; mi = c; }
        }
        #pragma unroll
        for (int off = 16; off >= 1; off >>= 1) {
            s  += __shfl_xor_sync(0xffffffffu, s,  off);
            sq += __shfl_xor_sync(0xffffffffu, sq, off);
            float om = __shfl_xor_sync(0xffffffffu, m,  off);
            int   oi = __shfl_xor_sync(0xffffffffu, mi, off);
            if (om > m || (om == m && oi < mi)) { m = om; mi = oi; }
        }
        int lab = labels[row];
        int labc = lab < 0 ? 0 : (lab >= C ? C - 1 : lab);
        float pl = rp[labc];
        float inv  = 1.f / s;
        float conf = m * inv;
        float bri  = sq * inv * inv - 2.f * pl * inv + 1.f;
        int   hit  = (mi == lab) ? 1 : 0;
        int bin = (int)ceilf(conf * (float)N_BINS) - 1;
        bin = bin < 0 ? 0 : (bin > N_BINS - 1 ? N_BINS - 1 : bin);
        if (lane == bin) { acc_count += 1.f; acc_conf += conf; acc_acc += (float)hit; }
        if (lane == 0) acc_bri += bri;
    }

    if (lane < N_BINS && acc_count > 0.f) {
        atomicAdd(&g_count[lane], (double)acc_count);
        atomicAdd(&g_conf[lane],  (double)acc_conf);
        atomicAdd(&g_acc[lane],   (double)acc_acc);
    }
    if (lane == 0 && acc_bri != 0.f) atomicAdd(&g_bri, (double)acc_bri);
}

__global__ void ece_final(float* __restrict__ out, int N) {
    if (threadIdx.x == 0) {
        double ece = 0.0, mx = 0.0;
        double invN = 1.0 / (double)N;
        #pragma unroll
        for (int b = 0; b < N_BINS; b++) {
            double c = g_count[b];
            if (c > 0.0) {
                double gap = fabs(g_conf[b] / c - g_acc[b] / c);
                ece += gap * c * invN;
                if (gap > mx) mx = gap;
            }
        }
        out[0] = (float)ece;
        out[1] = (float)mx;
        out[2] = (float)(g_bri * invN);
    }
}

extern "C" void kernel_launch(void* const* d_in, const int* in_sizes, int n_in,
                              void* d_out, int out_size) {
    int i_probs = 0, i_labels = 1;
    if (n_in >= 2 && in_sizes[1] > in_sizes[0]) { i_probs = 1; i_labels = 0; }
    const float* probs  = (const float*)d_in[i_probs];
    const int*   labels = (const int*)d_in[i_labels];
    int N = in_sizes[i_labels];
    int C = in_sizes[i_probs] / N;
    float* out = (float*)d_out;

    ece_init<<<1, 32>>>();

    if (C == 100) {
        // 4 blocks/SM x 8 warps: ~4.7K warps, double-buffered 4-row quads
        ece_main_c100<<<148 * 4, 256>>>((const float4*)probs, labels, N);
    } else {
        ece_main_generic<<<148 * 8, 256>>>(probs, labels, N, C);
    }

    ece_final<<<1, 32>>>(out, N);
}